// round 5
// baseline (speedup 1.0000x reference)
#include <cuda_runtime.h>
#include <cstdint>

#define BB 32
#define CC 128
#define HH 56
#define WW 56

// ---------------- scratch (module-static device memory; no allocs) ----------------
__device__ uint8_t g_ah[BB * HH * WW * CC];        // u8 high acts, NHWC (128 B/pixel)
__device__ uint8_t g_al4[BB * HH * WW * (CC / 2)]; // u4 low acts, NHWC nibble-packed (64 B/pixel)
__device__ int8_t  g_wh[CC * 9 * CC];              // s8 high weights [co][k][ci]
__device__ uint8_t g_wl4[CC * 9 * (CC / 2)];       // s4 low weights [co][k][ci/2] nibble-packed
__device__ float   g_fsh[CC];                      // fused scale high: s_w[co] * act_scale
__device__ float   g_fsl[CC];                      // fused scale low

// ---------------- K1: per-output-channel weight quantization ----------------
__global__ __launch_bounds__(256) void quant_weights_kernel(
    const float* __restrict__ w, const float* __restrict__ as_ptr,
    float nlev, int which)
{
    int co = blockIdx.x;
    int tid = threadIdx.x;
    const float* wc = w + co * (CC * 9);

    float mx = 0.f;
    for (int i = tid; i < CC * 9; i += 256) mx = fmaxf(mx, fabsf(wc[i]));
    __shared__ float red[256];
    red[tid] = mx;
    __syncthreads();
    for (int s = 128; s > 0; s >>= 1) {
        if (tid < s) red[tid] = fmaxf(red[tid], red[tid + s]);
        __syncthreads();
    }
    float s = red[0] / nlev;

    if (which == 0) {
        for (int i = tid; i < CC * 9; i += 256) {
            float q = rintf(wc[i] / s);
            q = fminf(fmaxf(q, -nlev), nlev);
            int ci = i / 9, k = i % 9;              // OIHW: i = ci*9 + k
            g_wh[(co * 9 + k) * CC + ci] = (int8_t)q;
        }
        if (tid == 0) g_fsh[co] = s * as_ptr[0];
    } else {
        for (int i = tid; i < (CC / 2) * 9; i += 256) {
            int ci2 = i / 9, k = i % 9;
            int ci = ci2 * 2;
            float q0 = fminf(fmaxf(rintf(wc[ci * 9 + k] / s), -nlev), nlev);
            float q1 = fminf(fmaxf(rintf(wc[(ci + 1) * 9 + k] / s), -nlev), nlev);
            uint8_t byt = (uint8_t)(((int)q0 & 0xF) | (((int)q1 & 0xF) << 4));
            g_wl4[(co * 9 + k) * (CC / 2) + ci2] = byt;
        }
        if (tid == 0) g_fsl[co] = s * as_ptr[0];
    }
}

// ---------------- K2: predictor mask + act fake-quant (u8 high, u4 low) ----------------
__global__ __launch_bounds__(256) void mask_quant_kernel(
    const float* __restrict__ x,
    const float* __restrict__ ash_p, const float* __restrict__ asl_p)
{
    int bw = blockIdx.x, bh = blockIdx.y, b = blockIdx.z;
    int tid = threadIdx.x;
    int h0 = bh * 8, w0 = bw * 8;

    __shared__ float sx[64][CC + 1];
    __shared__ uint8_t smask[CC];

    for (int i = tid; i < 64 * CC; i += 256) {
        int c = i >> 6, p = i & 63;
        sx[p][c] = x[((b * CC + c) * HH + h0 + (p >> 3)) * WW + w0 + (p & 7)];
    }
    __syncthreads();

    int lane = tid & 31, wrp = tid >> 5;
    for (int j = 0; j < 16; j++) {
        int c = wrp * 16 + j;
        float v = sx[lane][c] + sx[lane + 32][c];
        #pragma unroll
        for (int o = 16; o > 0; o >>= 1) v += __shfl_xor_sync(0xffffffffu, v, o);
        if (lane == 0) smask[c] = (v * (1.0f / 64.0f) >= 0.05f) ? 1 : 0;
    }
    __syncthreads();

    float ash = ash_p[0], asl = asl_p[0];
    // each i: one pixel x 8 channels -> 2 u32 of u8 high + 1 u32 of u4 low
    for (int i = tid; i < 64 * 16; i += 256) {
        int p = i >> 4, c8 = i & 15;
        int hh = h0 + (p >> 3), ww = w0 + (p & 7);
        unsigned qh0 = 0u, qh1 = 0u, ql4 = 0u;
        #pragma unroll
        for (int j = 0; j < 8; j++) {
            int c = c8 * 8 + j;
            float v = sx[p][c];
            bool m = smask[c] != 0;
            float fh = fminf(fmaxf(rintf(v / ash), 0.f), 255.f);
            float fl = fminf(fmaxf(rintf(v / asl), 0.f), 15.f);
            unsigned b8h = m ? (unsigned)fh : 0u;
            unsigned b4l = m ? 0u : (unsigned)fl;
            if (j < 4) qh0 |= b8h << (8 * j);
            else       qh1 |= b8h << (8 * (j - 4));
            ql4 |= b4l << (4 * j);
        }
        int pix = (b * HH + hh) * WW + ww;
        ((unsigned*)g_ah)[pix * 32 + c8 * 2]     = qh0;
        ((unsigned*)g_ah)[pix * 32 + c8 * 2 + 1] = qh1;
        ((unsigned*)g_al4)[pix * 16 + c8]        = ql4;
    }
}

// ---------------- K3: dual conv3x3 — u8s8 m16n8k32 (high) + u4s4 m16n8k64 (low) ----------------
// CTA: 64 pixels (8x8) x 128 co x both convs. 8 warps (2M x 4N), warp = 32pix x 32co.

#define ROWBH 144                         // high row stride (conflict-free: 36 words)
#define ROWBL 80                          // low  row stride (conflict-free: 20 words)
#define ACT_H_BYTES (100 * ROWBH)         // 14400
#define ACT_L_BYTES (100 * ROWBL)         // 8000
#define WH_STRIDE (CC * ROWBH)            // 18432
#define WL_STRIDE (CC * ROWBL)            // 10240
#define WSTG (WH_STRIDE + WL_STRIDE)      // 28672 per stage
#define CONV_SMEM (ACT_H_BYTES + ACT_L_BYTES + 2 * WSTG)   // 79744

__device__ __forceinline__ void mma_u8s8(int* c, const unsigned* a, unsigned b0, unsigned b1) {
    asm volatile(
        "mma.sync.aligned.m16n8k32.row.col.s32.u8.s8.s32 "
        "{%0,%1,%2,%3}, {%4,%5,%6,%7}, {%8,%9}, {%0,%1,%2,%3};"
        : "+r"(c[0]), "+r"(c[1]), "+r"(c[2]), "+r"(c[3])
        : "r"(a[0]), "r"(a[1]), "r"(a[2]), "r"(a[3]), "r"(b0), "r"(b1));
}

__device__ __forceinline__ void mma_u4s4(int* c, const unsigned* a, unsigned b0, unsigned b1) {
    asm volatile(
        "mma.sync.aligned.m16n8k64.row.col.s32.u4.s4.s32 "
        "{%0,%1,%2,%3}, {%4,%5,%6,%7}, {%8,%9}, {%0,%1,%2,%3};"
        : "+r"(c[0]), "+r"(c[1]), "+r"(c[2]), "+r"(c[3])
        : "r"(a[0]), "r"(a[1]), "r"(a[2]), "r"(a[3]), "r"(b0), "r"(b1));
}

__device__ __forceinline__ void stage_weights(char* dstbase, int k, int tid) {
    unsigned sdst = (unsigned)__cvta_generic_to_shared(dstbase);
    // high: 1024 chunks of 16B (128 co x 8)
    #pragma unroll
    for (int j = 0; j < 4; j++) {
        int i = tid + j * 256;
        int co = i >> 3, c16 = i & 7;
        const char* src = (const char*)g_wh + (co * 9 + k) * CC + c16 * 16;
        unsigned d = sdst + co * ROWBH + c16 * 16;
        asm volatile("cp.async.cg.shared.global [%0], [%1], 16;" :: "r"(d), "l"(src));
    }
    // low: 512 chunks of 16B (128 co x 4)
    #pragma unroll
    for (int j = 0; j < 2; j++) {
        int i = tid + j * 256;
        int co = i >> 2, c16 = i & 3;
        const char* src = (const char*)g_wl4 + (co * 9 + k) * (CC / 2) + c16 * 16;
        unsigned d = sdst + WH_STRIDE + co * ROWBL + c16 * 16;
        asm volatile("cp.async.cg.shared.global [%0], [%1], 16;" :: "r"(d), "l"(src));
    }
}

__global__ __launch_bounds__(256, 2) void conv_mma_kernel(float* __restrict__ out)
{
    extern __shared__ char smem[];
    char* s_ah = smem;                              // [pin(100)][144B]
    char* s_al = smem + ACT_H_BYTES;                // [pin(100)][80B]
    char* s_w  = smem + ACT_H_BYTES + ACT_L_BYTES;  // [buf][high 128x144 | low 128x80]

    int tid = threadIdx.x;
    int b = blockIdx.z;
    int h0 = blockIdx.y * 8, w0 = blockIdx.x * 8;

    // preload activation halo tiles: high 800 + low 400 uint4
    #pragma unroll
    for (int j = 0; j < 5; j++) {
        int i = tid + j * 256;
        if (i < 1200) {
            if (i < 800) {
                int p = i >> 3, c16 = i & 7;
                int pr = p / 10 - 1 + h0, pc = p % 10 - 1 + w0;
                uint4 v = make_uint4(0u, 0u, 0u, 0u);
                if (pr >= 0 && pr < HH && pc >= 0 && pc < WW)
                    v = ((const uint4*)g_ah)[((b * HH + pr) * WW + pc) * 8 + c16];
                *(uint4*)(s_ah + p * ROWBH + c16 * 16) = v;
            } else {
                int r = i - 800;
                int p = r >> 2, c16 = r & 3;
                int pr = p / 10 - 1 + h0, pc = p % 10 - 1 + w0;
                uint4 v = make_uint4(0u, 0u, 0u, 0u);
                if (pr >= 0 && pr < HH && pc >= 0 && pc < WW)
                    v = ((const uint4*)g_al4)[((b * HH + pr) * WW + pc) * 4 + c16];
                *(uint4*)(s_al + p * ROWBL + c16 * 16) = v;
            }
        }
    }

    stage_weights(s_w, 0, tid);
    asm volatile("cp.async.commit_group;" ::: "memory");

    int lane = tid & 31, warp = tid >> 5;
    int warpM = warp >> 2;       // 0..1 : 32-pixel half
    int warpN = warp & 3;        // 0..3 : 32-co group
    int g = lane >> 2, t = lane & 3;

    int acch[2][4][4], accl[2][4][4];   // [mtile][ntile][c]
    #pragma unroll
    for (int mt = 0; mt < 2; mt++)
        #pragma unroll
        for (int nt = 0; nt < 4; nt++)
            #pragma unroll
            for (int q = 0; q < 4; q++) { acch[mt][nt][q] = 0; accl[mt][nt][q] = 0; }

    // pixel coords: p = warpM*32 + mt*16 + hf*8 + g  (base multiple of 8 -> pw = g)
    int phh[2][2];
    #pragma unroll
    for (int mt = 0; mt < 2; mt++)
        #pragma unroll
        for (int hf = 0; hf < 2; hf++)
            phh[mt][hf] = (warpM * 32 + mt * 16 + hf * 8 + g) >> 3;

    #pragma unroll 1
    for (int k9 = 0; k9 < 9; k9++) {
        asm volatile("cp.async.wait_group 0;" ::: "memory");
        __syncthreads();
        char* wcur = s_w + (k9 & 1) * WSTG;
        if (k9 < 8) {
            stage_weights(s_w + ((k9 + 1) & 1) * WSTG, k9 + 1, tid);
            asm volatile("cp.async.commit_group;" ::: "memory");
        }
        int kh = k9 / 3, kw = k9 - kh * 3;
        int pin[2][2];
        #pragma unroll
        for (int mt = 0; mt < 2; mt++)
            #pragma unroll
            for (int hf = 0; hf < 2; hf++)
                pin[mt][hf] = (phh[mt][hf] + kh) * 10 + g + kw;

        // ---- high conv: u8 x s8, K=128 -> 4 chunks of k32 ----
        #pragma unroll
        for (int chunk = 0; chunk < 4; chunk++) {
            unsigned a[2][4];
            const char* abase = s_ah + chunk * 32 + t * 4;
            #pragma unroll
            for (int mt = 0; mt < 2; mt++) {
                a[mt][0] = *(const unsigned*)(abase + pin[mt][0] * ROWBH);
                a[mt][1] = *(const unsigned*)(abase + pin[mt][1] * ROWBH);
                a[mt][2] = *(const unsigned*)(abase + pin[mt][0] * ROWBH + 16);
                a[mt][3] = *(const unsigned*)(abase + pin[mt][1] * ROWBH + 16);
            }
            const char* wb0 = wcur + chunk * 32 + t * 4;
            #pragma unroll
            for (int nt = 0; nt < 4; nt++) {
                int co = warpN * 32 + nt * 8 + g;
                const char* wb = wb0 + co * ROWBH;
                unsigned b0 = *(const unsigned*)wb;
                unsigned b1 = *(const unsigned*)(wb + 16);
                #pragma unroll
                for (int mt = 0; mt < 2; mt++)
                    mma_u8s8(acch[mt][nt], a[mt], b0, b1);
            }
        }
        // ---- low conv: u4 x s4, K=128 -> 2 chunks of k64 ----
        #pragma unroll
        for (int chunk = 0; chunk < 2; chunk++) {
            unsigned a[2][4];
            const char* abase = s_al + chunk * 32 + t * 4;
            #pragma unroll
            for (int mt = 0; mt < 2; mt++) {
                a[mt][0] = *(const unsigned*)(abase + pin[mt][0] * ROWBL);
                a[mt][1] = *(const unsigned*)(abase + pin[mt][1] * ROWBL);
                a[mt][2] = *(const unsigned*)(abase + pin[mt][0] * ROWBL + 16);
                a[mt][3] = *(const unsigned*)(abase + pin[mt][1] * ROWBL + 16);
            }
            const char* wb0 = wcur + WH_STRIDE + chunk * 32 + t * 4;
            #pragma unroll
            for (int nt = 0; nt < 4; nt++) {
                int co = warpN * 32 + nt * 8 + g;
                const char* wb = wb0 + co * ROWBL;
                unsigned b0 = *(const unsigned*)wb;
                unsigned b1 = *(const unsigned*)(wb + 16);
                #pragma unroll
                for (int mt = 0; mt < 2; mt++)
                    mma_u4s4(accl[mt][nt], a[mt], b0, b1);
            }
        }
    }

    // epilogue: y = fsh[co]*acc_h + fsl[co]*acc_l  -> NCHW fp32
    #pragma unroll
    for (int nt = 0; nt < 4; nt++) {
        int co0 = warpN * 32 + nt * 8 + t * 2;
        float sh0 = g_fsh[co0],     sl0 = g_fsl[co0];
        float sh1 = g_fsh[co0 + 1], sl1 = g_fsl[co0 + 1];
        #pragma unroll
        for (int mt = 0; mt < 2; mt++) {
            #pragma unroll
            for (int hf = 0; hf < 2; hf++) {
                int p = warpM * 32 + mt * 16 + hf * 8 + g;
                int oh = h0 + (p >> 3), ow = w0 + (p & 7);
                int q = hf * 2;
                float y0 = sh0 * (float)acch[mt][nt][q]     + sl0 * (float)accl[mt][nt][q];
                float y1 = sh1 * (float)acch[mt][nt][q + 1] + sl1 * (float)accl[mt][nt][q + 1];
                out[((b * CC + co0) * HH + oh) * WW + ow] = y0;
                out[((b * CC + co0 + 1) * HH + oh) * WW + ow] = y1;
            }
        }
    }
}

// ---------------- launch ----------------
extern "C" void kernel_launch(void* const* d_in, const int* in_sizes, int n_in,
                              void* d_out, int out_size)
{
    const float* x      = (const float*)d_in[0];
    const float* w_high = (const float*)d_in[1];
    const float* w_low  = (const float*)d_in[2];
    const float* as_h   = (const float*)d_in[3];
    const float* as_l   = (const float*)d_in[4];
    float* out = (float*)d_out;

    cudaFuncSetAttribute(conv_mma_kernel,
                         cudaFuncAttributeMaxDynamicSharedMemorySize, CONV_SMEM);

    quant_weights_kernel<<<CC, 256>>>(w_high, as_h, 127.0f, 0);
    quant_weights_kernel<<<CC, 256>>>(w_low,  as_l,   7.0f, 1);
    mask_quant_kernel<<<dim3(WW / 8, HH / 8, BB), 256>>>(x, as_h, as_l);
    conv_mma_kernel<<<dim3(WW / 8, HH / 8, BB), 256, CONV_SMEM>>>(out);
}

// round 6
// speedup vs baseline: 1.0460x; 1.0460x over previous
#include <cuda_runtime.h>
#include <cstdint>

#define BB 32
#define CC 128
#define HH 56
#define WW 56

// ---------------- scratch (module-static device memory; no allocs) ----------------
__device__ uint8_t g_ah[BB * HH * WW * CC];   // u8 high acts, NHWC (128 B/pixel)
__device__ uint8_t g_al[BB * HH * WW * CC];   // u8 low  acts, NHWC (128 B/pixel)
__device__ int8_t  g_wh[CC * 9 * CC];         // s8 high weights [co][k][ci]
__device__ int8_t  g_wlT[9 * 32 * CC * 4];    // s8 low weights  [k][ci4][co][ci&3]
__device__ float   g_fsh[CC];                 // fused scale high
__device__ float   g_fsl[CC];                 // fused scale low

__device__ __forceinline__ int dp4a_us(unsigned a, unsigned b, int c) {
    int r;
    asm("dp4a.u32.s32 %0, %1, %2, %3;" : "=r"(r) : "r"(a), "r"(b), "r"(c));
    return r;
}

// ---------------- K1: per-output-channel weight quantization ----------------
__global__ __launch_bounds__(256) void quant_weights_kernel(
    const float* __restrict__ w, const float* __restrict__ as_ptr,
    float nlev, int which)
{
    int co = blockIdx.x;
    int tid = threadIdx.x;
    const float* wc = w + co * (CC * 9);

    float mx = 0.f;
    for (int i = tid; i < CC * 9; i += 256) mx = fmaxf(mx, fabsf(wc[i]));
    __shared__ float red[256];
    red[tid] = mx;
    __syncthreads();
    for (int s = 128; s > 0; s >>= 1) {
        if (tid < s) red[tid] = fmaxf(red[tid], red[tid + s]);
        __syncthreads();
    }
    float s = red[0] / nlev;

    for (int i = tid; i < CC * 9; i += 256) {
        float q = rintf(wc[i] / s);
        q = fminf(fmaxf(q, -nlev), nlev);
        int ci = i / 9, k = i % 9;                 // OIHW: i = ci*9 + k
        if (which == 0)
            g_wh[(co * 9 + k) * CC + ci] = (int8_t)q;
        else
            g_wlT[(k * 32 + (ci >> 2)) * 512 + co * 4 + (ci & 3)] = (int8_t)q;
    }
    if (tid == 0) {
        if (which) g_fsl[co] = s * as_ptr[0];
        else       g_fsh[co] = s * as_ptr[0];
    }
}

// ---------------- K2: predictor mask + activation fake-quant -> NHWC uint8 ----------------
__global__ __launch_bounds__(256) void mask_quant_kernel(
    const float* __restrict__ x,
    const float* __restrict__ ash_p, const float* __restrict__ asl_p)
{
    int bw = blockIdx.x, bh = blockIdx.y, b = blockIdx.z;
    int tid = threadIdx.x;
    int h0 = bh * 8, w0 = bw * 8;

    __shared__ float sx[64][CC + 1];
    __shared__ uint8_t smask[CC];

    for (int i = tid; i < 64 * CC; i += 256) {
        int c = i >> 6, p = i & 63;
        sx[p][c] = x[((b * CC + c) * HH + h0 + (p >> 3)) * WW + w0 + (p & 7)];
    }
    __syncthreads();

    int lane = tid & 31, wrp = tid >> 5;
    for (int j = 0; j < 16; j++) {
        int c = wrp * 16 + j;
        float v = sx[lane][c] + sx[lane + 32][c];
        #pragma unroll
        for (int o = 16; o > 0; o >>= 1) v += __shfl_xor_sync(0xffffffffu, v, o);
        if (lane == 0) smask[c] = (v * (1.0f / 64.0f) >= 0.05f) ? 1 : 0;
    }
    __syncthreads();

    float ash = ash_p[0], asl = asl_p[0];
    for (int i = tid; i < 64 * (CC / 4); i += 256) {
        int p = i >> 5, c4 = (i & 31);
        int hh = h0 + (p >> 3), ww = w0 + (p & 7);
        unsigned qh = 0u, ql = 0u;
        #pragma unroll
        for (int j = 0; j < 4; j++) {
            int c = c4 * 4 + j;
            float v = sx[p][c];
            bool m = smask[c] != 0;
            float fh = fminf(fmaxf(rintf(v / ash), 0.f), 255.f);
            float fl = fminf(fmaxf(rintf(v / asl), 0.f), 15.f);
            unsigned b8h = m ? (unsigned)fh : 0u;
            unsigned b8l = m ? 0u : (unsigned)fl;
            qh |= b8h << (8 * j);
            ql |= b8l << (8 * j);
        }
        int base = ((b * HH + hh) * WW + ww) * (CC / 4) + c4;
        ((unsigned*)g_ah)[base] = qh;
        ((unsigned*)g_al)[base] = ql;
    }
}

// ---------------- K3: hybrid conv3x3 — high via mma (tensor pipe), low via dp4a (fma pipe) ----------------
// CTA: 512 thr = 16 warps (4M x 4N). Tile: 64 pixels (8x8) x 128 co x both convs.
// Warp: 16 pix x 32 co. dp4a accumulators mirror mma C-fragment positions exactly.

#define ROWB 144
#define ACT_H_OFF 0
#define ACT_L_OFF 14400                         // 100*144
#define WH_OFF 28800                            // act 2*14400
#define WH_BUF 18432                            // 128*144
#define WL_OFF (28800 + 2 * 18432)              // 65664
#define WL_BUF 16384                            // 32*128*4
#define CONV_SMEM (WL_OFF + 2 * WL_BUF)         // 98432

__device__ __forceinline__ void mma_u8s8(int* c, const unsigned* a, unsigned b0, unsigned b1) {
    asm volatile(
        "mma.sync.aligned.m16n8k32.row.col.s32.u8.s8.s32 "
        "{%0,%1,%2,%3}, {%4,%5,%6,%7}, {%8,%9}, {%0,%1,%2,%3};"
        : "+r"(c[0]), "+r"(c[1]), "+r"(c[2]), "+r"(c[3])
        : "r"(a[0]), "r"(a[1]), "r"(a[2]), "r"(a[3]), "r"(b0), "r"(b1));
}

__device__ __forceinline__ void stage_weights(char* smem, int buf, int k, int tid) {
    unsigned sb = (unsigned)__cvta_generic_to_shared(smem);
    // high: 1024 chunks of 16B (128 co x 8)
    #pragma unroll
    for (int j = 0; j < 2; j++) {
        int i = tid + j * 512;
        int co = i >> 3, c16 = i & 7;
        const char* src = (const char*)g_wh + (co * 9 + k) * CC + c16 * 16;
        unsigned d = sb + WH_OFF + buf * WH_BUF + co * ROWB + c16 * 16;
        asm volatile("cp.async.cg.shared.global [%0], [%1], 16;" :: "r"(d), "l"(src));
    }
    // low (transposed [ci4][co] layout): 1024 chunks of 16B, contiguous per tap
    #pragma unroll
    for (int j = 0; j < 2; j++) {
        int i = tid + j * 512;
        const char* src = (const char*)g_wlT + k * WL_BUF + i * 16;
        unsigned d = sb + WL_OFF + buf * WL_BUF + i * 16;
        asm volatile("cp.async.cg.shared.global [%0], [%1], 16;" :: "r"(d), "l"(src));
    }
}

__global__ __launch_bounds__(512, 1) void conv_hybrid_kernel(float* __restrict__ out)
{
    extern __shared__ __align__(16) char smem[];
    unsigned sbase = (unsigned)__cvta_generic_to_shared(smem);

    int tid = threadIdx.x;
    int b = blockIdx.z;
    int h0 = blockIdx.y * 8, w0 = blockIdx.x * 8;

    // act halo tiles (both convs): 1600 16B chunks; invalid -> zero store
    #pragma unroll
    for (int j = 0; j < 4; j++) {
        int i = tid + j * 512;
        if (i < 1600) {
            int cv = i / 800, r = i % 800;
            int p = r >> 3, c16 = r & 7;
            int pr = p / 10 - 1 + h0, pc = p % 10 - 1 + w0;
            char* dgen = smem + (cv ? ACT_L_OFF : ACT_H_OFF) + p * ROWB + c16 * 16;
            if (pr >= 0 && pr < HH && pc >= 0 && pc < WW) {
                const char* src = (const char*)(cv ? g_al : g_ah)
                                  + ((size_t)((b * HH + pr) * WW + pc)) * 128 + c16 * 16;
                unsigned d = (unsigned)__cvta_generic_to_shared(dgen);
                asm volatile("cp.async.cg.shared.global [%0], [%1], 16;" :: "r"(d), "l"(src));
            } else {
                *(uint4*)dgen = make_uint4(0u, 0u, 0u, 0u);
            }
        }
    }
    stage_weights(smem, 0, 0, tid);
    asm volatile("cp.async.commit_group;" ::: "memory");

    int lane = tid & 31, warp = tid >> 5;
    int wm = warp >> 2;          // 0..3 : 16-pixel group
    int wn = warp & 3;           // 0..3 : 32-co group
    int g = lane >> 2, t = lane & 3;

    int acch[4][4], accl[4][4];
    #pragma unroll
    for (int nt = 0; nt < 4; nt++)
        #pragma unroll
        for (int q = 0; q < 4; q++) { acch[nt][q] = 0; accl[nt][q] = 0; }

    // pixel rows: p0 = wm*16 + g (ph=2wm, pw=g), p1 = p0 + 8 (ph=2wm+1)
    const char* s_ah = smem + ACT_H_OFF;
    const char* s_al = smem + ACT_L_OFF;

    #pragma unroll 1
    for (int k9 = 0; k9 < 9; k9++) {
        asm volatile("cp.async.wait_group 0;" ::: "memory");
        __syncthreads();
        int buf = k9 & 1;
        if (k9 < 8) {
            stage_weights(smem, buf ^ 1, k9 + 1, tid);
            asm volatile("cp.async.commit_group;" ::: "memory");
        }
        int kh = k9 / 3, kw = k9 - kh * 3;
        int pin0 = (2 * wm + kh) * 10 + g + kw;
        int pin1 = pin0 + 10;

        // ---- high conv: tensor pipe (m16n8k32 u8s8) ----
        const char* wcur = smem + WH_OFF + buf * WH_BUF;
        #pragma unroll
        for (int chunk = 0; chunk < 4; chunk++) {
            unsigned a[4];
            const char* abase = s_ah + chunk * 32 + t * 4;
            a[0] = *(const unsigned*)(abase + pin0 * ROWB);
            a[1] = *(const unsigned*)(abase + pin1 * ROWB);
            a[2] = *(const unsigned*)(abase + pin0 * ROWB + 16);
            a[3] = *(const unsigned*)(abase + pin1 * ROWB + 16);
            #pragma unroll
            for (int nt = 0; nt < 4; nt++) {
                int co = wn * 32 + nt * 8 + g;
                const char* wb = wcur + co * ROWB + chunk * 32 + t * 4;
                unsigned b0 = *(const unsigned*)wb;
                unsigned b1 = *(const unsigned*)(wb + 16);
                mma_u8s8(acch[nt], a, b0, b1);
            }
        }

        // ---- low conv: fma pipe (dp4a), acc layout mirrors mma C-fragments ----
        const unsigned* wl = (const unsigned*)(smem + WL_OFF + buf * WL_BUF);
        #pragma unroll
        for (int seg = 0; seg < 8; seg++) {
            uint4 a0 = *(const uint4*)(s_al + pin0 * ROWB + seg * 16);
            uint4 a1 = *(const uint4*)(s_al + pin1 * ROWB + seg * 16);
            const unsigned aw0[4] = {a0.x, a0.y, a0.z, a0.w};
            const unsigned aw1[4] = {a1.x, a1.y, a1.z, a1.w};
            #pragma unroll
            for (int q = 0; q < 4; q++) {
                int ci4 = seg * 4 + q;
                #pragma unroll
                for (int nt = 0; nt < 4; nt++) {
                    // weight words for co = wn*32 + nt*8 + t*2 (+1), this ci4
                    uint2 wv = *(const uint2*)(wl + ci4 * 128 + wn * 32 + nt * 8 + t * 2);
                    accl[nt][0] = dp4a_us(aw0[q], wv.x, accl[nt][0]);
                    accl[nt][1] = dp4a_us(aw0[q], wv.y, accl[nt][1]);
                    accl[nt][2] = dp4a_us(aw1[q], wv.x, accl[nt][2]);
                    accl[nt][3] = dp4a_us(aw1[q], wv.y, accl[nt][3]);
                }
            }
        }
    }

    // epilogue: y = fsh*acc_h + fsl*acc_l -> NCHW fp32 (both acc sets share layout)
    int p0 = wm * 16 + g;
    int oh0 = h0 + (p0 >> 3), ow = w0 + (p0 & 7);
    int oh1 = oh0 + 1;                               // p1 = p0+8 -> next row
    #pragma unroll
    for (int nt = 0; nt < 4; nt++) {
        int co0 = wn * 32 + nt * 8 + t * 2;
        float sh0 = g_fsh[co0],     sl0 = g_fsl[co0];
        float sh1 = g_fsh[co0 + 1], sl1 = g_fsl[co0 + 1];
        out[((b * CC + co0) * HH + oh0) * WW + ow] =
            sh0 * (float)acch[nt][0] + sl0 * (float)accl[nt][0];
        out[((b * CC + co0 + 1) * HH + oh0) * WW + ow] =
            sh1 * (float)acch[nt][1] + sl1 * (float)accl[nt][1];
        out[((b * CC + co0) * HH + oh1) * WW + ow] =
            sh0 * (float)acch[nt][2] + sl0 * (float)accl[nt][2];
        out[((b * CC + co0 + 1) * HH + oh1) * WW + ow] =
            sh1 * (float)acch[nt][3] + sl1 * (float)accl[nt][3];
    }
}

// ---------------- launch ----------------
extern "C" void kernel_launch(void* const* d_in, const int* in_sizes, int n_in,
                              void* d_out, int out_size)
{
    const float* x      = (const float*)d_in[0];
    const float* w_high = (const float*)d_in[1];
    const float* w_low  = (const float*)d_in[2];
    const float* as_h   = (const float*)d_in[3];
    const float* as_l   = (const float*)d_in[4];
    float* out = (float*)d_out;

    cudaFuncSetAttribute(conv_hybrid_kernel,
                         cudaFuncAttributeMaxDynamicSharedMemorySize, CONV_SMEM);

    quant_weights_kernel<<<CC, 256>>>(w_high, as_h, 127.0f, 0);
    quant_weights_kernel<<<CC, 256>>>(w_low,  as_l,   7.0f, 1);
    mask_quant_kernel<<<dim3(WW / 8, HH / 8, BB), 256>>>(x, as_h, as_l);
    conv_hybrid_kernel<<<dim3(WW / 8, HH / 8, BB), 512, CONV_SMEM>>>(out);
}

// round 7
// speedup vs baseline: 1.4011x; 1.3396x over previous
#include <cuda_runtime.h>
#include <cstdint>

#define BB 32
#define CC 128
#define HH 56
#define WW 56

// ---------------- scratch (module-static device memory; no allocs) ----------------
__device__ uint8_t g_ah[BB * HH * WW * CC];   // u8 high acts, NHWC (128 B/pixel)
__device__ uint8_t g_al[BB * HH * WW * CC];   // u8 low  acts, NHWC (128 B/pixel)
__device__ int8_t  g_wh[CC * 9 * CC];         // s8 high weights [co][k][ci]
__device__ int8_t  g_wlT[9 * 32 * CC * 4];    // s8 low weights  [k][ci4][co][ci&3]
__device__ float   g_fsh[CC];                 // fused scale high
__device__ float   g_fsl[CC];                 // fused scale low

__device__ __forceinline__ int dp4a_us(unsigned a, unsigned b, int c) {
    int r;
    asm("dp4a.u32.s32 %0, %1, %2, %3;" : "=r"(r) : "r"(a), "r"(b), "r"(c));
    return r;
}

// ---------------- K1: per-output-channel weight quantization ----------------
__global__ __launch_bounds__(256) void quant_weights_kernel(
    const float* __restrict__ w, const float* __restrict__ as_ptr,
    float nlev, int which)
{
    int co = blockIdx.x;
    int tid = threadIdx.x;
    const float* wc = w + co * (CC * 9);

    float mx = 0.f;
    for (int i = tid; i < CC * 9; i += 256) mx = fmaxf(mx, fabsf(wc[i]));
    __shared__ float red[256];
    red[tid] = mx;
    __syncthreads();
    for (int s = 128; s > 0; s >>= 1) {
        if (tid < s) red[tid] = fmaxf(red[tid], red[tid + s]);
        __syncthreads();
    }
    float s = red[0] / nlev;

    for (int i = tid; i < CC * 9; i += 256) {
        float q = rintf(wc[i] / s);
        q = fminf(fmaxf(q, -nlev), nlev);
        int ci = i / 9, k = i % 9;                 // OIHW: i = ci*9 + k
        if (which == 0)
            g_wh[(co * 9 + k) * CC + ci] = (int8_t)q;
        else
            g_wlT[(k * 32 + (ci >> 2)) * 512 + co * 4 + (ci & 3)] = (int8_t)q;
    }
    if (tid == 0) {
        if (which) g_fsl[co] = s * as_ptr[0];
        else       g_fsh[co] = s * as_ptr[0];
    }
}

// ---------------- K2: predictor mask + activation fake-quant -> NHWC uint8 ----------------
__global__ __launch_bounds__(256) void mask_quant_kernel(
    const float* __restrict__ x,
    const float* __restrict__ ash_p, const float* __restrict__ asl_p)
{
    int bw = blockIdx.x, bh = blockIdx.y, b = blockIdx.z;
    int tid = threadIdx.x;
    int h0 = bh * 8, w0 = bw * 8;

    __shared__ float sx[64][CC + 1];
    __shared__ uint8_t smask[CC];

    for (int i = tid; i < 64 * CC; i += 256) {
        int c = i >> 6, p = i & 63;
        sx[p][c] = x[((b * CC + c) * HH + h0 + (p >> 3)) * WW + w0 + (p & 7)];
    }
    __syncthreads();

    int lane = tid & 31, wrp = tid >> 5;
    for (int j = 0; j < 16; j++) {
        int c = wrp * 16 + j;
        float v = sx[lane][c] + sx[lane + 32][c];
        #pragma unroll
        for (int o = 16; o > 0; o >>= 1) v += __shfl_xor_sync(0xffffffffu, v, o);
        if (lane == 0) smask[c] = (v * (1.0f / 64.0f) >= 0.05f) ? 1 : 0;
    }
    __syncthreads();

    float ash = ash_p[0], asl = asl_p[0];
    for (int i = tid; i < 64 * (CC / 4); i += 256) {
        int p = i >> 5, c4 = (i & 31);
        int hh = h0 + (p >> 3), ww = w0 + (p & 7);
        unsigned qh = 0u, ql = 0u;
        #pragma unroll
        for (int j = 0; j < 4; j++) {
            int c = c4 * 4 + j;
            float v = sx[p][c];
            bool m = smask[c] != 0;
            float fh = fminf(fmaxf(rintf(v / ash), 0.f), 255.f);
            float fl = fminf(fmaxf(rintf(v / asl), 0.f), 15.f);
            unsigned b8h = m ? (unsigned)fh : 0u;
            unsigned b8l = m ? 0u : (unsigned)fl;
            qh |= b8h << (8 * j);
            ql |= b8l << (8 * j);
        }
        int base = ((b * HH + hh) * WW + ww) * (CC / 4) + c4;
        ((unsigned*)g_ah)[base] = qh;
        ((unsigned*)g_al)[base] = ql;
    }
}

// ---------------- K3: hybrid conv3x3 — high via mma (tensor), low via dp4a (fma) ----------------
// CTA: 256 thr = 8 warps (4M x 2N). Tile: 64 pixels (8x8) x 64 co x both convs.
// 3 CTAs/SM: barriers idle only 8 warps; co-resident CTAs keep pipes fed.

#define ROWB 144
#define ACT_H_OFF 0
#define ACT_L_OFF 14400                         // 100*144
#define WH_OFF 28800                            // act 2*14400
#define WH_BUF 9216                             // 64*144
#define WL_OFF (28800 + 2 * 9216)               // 47232
#define WL_BUF 8192                             // 32*64*4
#define CONV_SMEM (WL_OFF + 2 * WL_BUF)         // 63616

__device__ __forceinline__ void mma_u8s8(int* c, const unsigned* a, unsigned b0, unsigned b1) {
    asm volatile(
        "mma.sync.aligned.m16n8k32.row.col.s32.u8.s8.s32 "
        "{%0,%1,%2,%3}, {%4,%5,%6,%7}, {%8,%9}, {%0,%1,%2,%3};"
        : "+r"(c[0]), "+r"(c[1]), "+r"(c[2]), "+r"(c[3])
        : "r"(a[0]), "r"(a[1]), "r"(a[2]), "r"(a[3]), "r"(b0), "r"(b1));
}

__device__ __forceinline__ void stage_weights(char* smem, int buf, int k, int co0, int tid) {
    unsigned sb = (unsigned)__cvta_generic_to_shared(smem);
    // high: 512 chunks of 16B (64 co x 8)
    #pragma unroll
    for (int j = 0; j < 2; j++) {
        int i = tid + j * 256;
        int co = i >> 3, c16 = i & 7;
        const char* src = (const char*)g_wh + ((co0 + co) * 9 + k) * CC + c16 * 16;
        unsigned d = sb + WH_OFF + buf * WH_BUF + co * ROWB + c16 * 16;
        asm volatile("cp.async.cg.shared.global [%0], [%1], 16;" :: "r"(d), "l"(src));
    }
    // low (transposed [ci4][co][4]): 512 chunks of 16B (32 ci4 x 16)
    #pragma unroll
    for (int j = 0; j < 2; j++) {
        int i = tid + j * 256;
        int ci4 = i >> 4, c16 = i & 15;
        const char* src = (const char*)g_wlT + (k * 32 + ci4) * 512 + co0 * 4 + c16 * 16;
        unsigned d = sb + WL_OFF + buf * WL_BUF + ci4 * 256 + c16 * 16;
        asm volatile("cp.async.cg.shared.global [%0], [%1], 16;" :: "r"(d), "l"(src));
    }
}

__global__ __launch_bounds__(256, 3) void conv_hybrid_kernel(float* __restrict__ out)
{
    extern __shared__ __align__(16) char smem[];

    int tid = threadIdx.x;
    int bz = blockIdx.z;
    int b = bz >> 1;
    int co0 = (bz & 1) * 64;
    int h0 = blockIdx.y * 8, w0 = blockIdx.x * 8;

    // act halo tiles (both convs): 1600 16B chunks; invalid -> zero store
    #pragma unroll
    for (int j = 0; j < 7; j++) {
        int i = tid + j * 256;
        if (i < 1600) {
            int cv = i / 800, r = i % 800;
            int p = r >> 3, c16 = r & 7;
            int pr = p / 10 - 1 + h0, pc = p % 10 - 1 + w0;
            char* dgen = smem + (cv ? ACT_L_OFF : ACT_H_OFF) + p * ROWB + c16 * 16;
            if (pr >= 0 && pr < HH && pc >= 0 && pc < WW) {
                const char* src = (const char*)(cv ? g_al : g_ah)
                                  + ((size_t)((b * HH + pr) * WW + pc)) * 128 + c16 * 16;
                unsigned d = (unsigned)__cvta_generic_to_shared(dgen);
                asm volatile("cp.async.cg.shared.global [%0], [%1], 16;" :: "r"(d), "l"(src));
            } else {
                *(uint4*)dgen = make_uint4(0u, 0u, 0u, 0u);
            }
        }
    }
    stage_weights(smem, 0, 0, co0, tid);
    asm volatile("cp.async.commit_group;" ::: "memory");

    int lane = tid & 31, warp = tid >> 5;
    int wm = warp >> 1;          // 0..3 : 16-pixel group
    int wn = warp & 1;           // 0..1 : 32-co group
    int g = lane >> 2, t = lane & 3;

    int acch[4][4], accl[4][4];
    #pragma unroll
    for (int nt = 0; nt < 4; nt++)
        #pragma unroll
        for (int q = 0; q < 4; q++) { acch[nt][q] = 0; accl[nt][q] = 0; }

    const char* s_ah = smem + ACT_H_OFF;
    const char* s_al = smem + ACT_L_OFF;

    #pragma unroll 1
    for (int k9 = 0; k9 < 9; k9++) {
        asm volatile("cp.async.wait_group 0;" ::: "memory");
        __syncthreads();
        int buf = k9 & 1;
        if (k9 < 8) {
            stage_weights(smem, buf ^ 1, k9 + 1, co0, tid);
            asm volatile("cp.async.commit_group;" ::: "memory");
        }
        int kh = k9 / 3, kw = k9 - kh * 3;
        int pin0 = (2 * wm + kh) * 10 + g + kw;
        int pin1 = pin0 + 10;

        // ---- high conv: tensor pipe (m16n8k32 u8s8) ----
        const char* wcur = smem + WH_OFF + buf * WH_BUF;
        #pragma unroll
        for (int chunk = 0; chunk < 4; chunk++) {
            unsigned a[4];
            const char* abase = s_ah + chunk * 32 + t * 4;
            a[0] = *(const unsigned*)(abase + pin0 * ROWB);
            a[1] = *(const unsigned*)(abase + pin1 * ROWB);
            a[2] = *(const unsigned*)(abase + pin0 * ROWB + 16);
            a[3] = *(const unsigned*)(abase + pin1 * ROWB + 16);
            #pragma unroll
            for (int nt = 0; nt < 4; nt++) {
                int co = wn * 32 + nt * 8 + g;
                const char* wb = wcur + co * ROWB + chunk * 32 + t * 4;
                unsigned b0 = *(const unsigned*)wb;
                unsigned b1 = *(const unsigned*)(wb + 16);
                mma_u8s8(acch[nt], a, b0, b1);
            }
        }

        // ---- low conv: fma pipe (dp4a), acc layout mirrors mma C-fragments ----
        const unsigned* wl = (const unsigned*)(smem + WL_OFF + buf * WL_BUF);
        #pragma unroll
        for (int seg = 0; seg < 8; seg++) {
            uint4 a0 = *(const uint4*)(s_al + pin0 * ROWB + seg * 16);
            uint4 a1 = *(const uint4*)(s_al + pin1 * ROWB + seg * 16);
            const unsigned aw0[4] = {a0.x, a0.y, a0.z, a0.w};
            const unsigned aw1[4] = {a1.x, a1.y, a1.z, a1.w};
            #pragma unroll
            for (int q = 0; q < 4; q++) {
                int ci4 = seg * 4 + q;
                #pragma unroll
                for (int nt = 0; nt < 4; nt++) {
                    uint2 wv = *(const uint2*)(wl + ci4 * 64 + wn * 32 + nt * 8 + t * 2);
                    accl[nt][0] = dp4a_us(aw0[q], wv.x, accl[nt][0]);
                    accl[nt][1] = dp4a_us(aw0[q], wv.y, accl[nt][1]);
                    accl[nt][2] = dp4a_us(aw1[q], wv.x, accl[nt][2]);
                    accl[nt][3] = dp4a_us(aw1[q], wv.y, accl[nt][3]);
                }
            }
        }
    }

    // epilogue: y = fsh*acc_h + fsl*acc_l -> NCHW fp32
    int p0 = wm * 16 + g;
    int oh0 = h0 + (p0 >> 3), ow = w0 + (p0 & 7);
    int oh1 = oh0 + 1;                               // p1 = p0+8 -> next row
    #pragma unroll
    for (int nt = 0; nt < 4; nt++) {
        int cg0 = co0 + wn * 32 + nt * 8 + t * 2;
        float sh0 = g_fsh[cg0],     sl0 = g_fsl[cg0];
        float sh1 = g_fsh[cg0 + 1], sl1 = g_fsl[cg0 + 1];
        out[((b * CC + cg0) * HH + oh0) * WW + ow] =
            sh0 * (float)acch[nt][0] + sl0 * (float)accl[nt][0];
        out[((b * CC + cg0 + 1) * HH + oh0) * WW + ow] =
            sh1 * (float)acch[nt][1] + sl1 * (float)accl[nt][1];
        out[((b * CC + cg0) * HH + oh1) * WW + ow] =
            sh0 * (float)acch[nt][2] + sl0 * (float)accl[nt][2];
        out[((b * CC + cg0 + 1) * HH + oh1) * WW + ow] =
            sh1 * (float)acch[nt][3] + sl1 * (float)accl[nt][3];
    }
}

// ---------------- launch ----------------
extern "C" void kernel_launch(void* const* d_in, const int* in_sizes, int n_in,
                              void* d_out, int out_size)
{
    const float* x      = (const float*)d_in[0];
    const float* w_high = (const float*)d_in[1];
    const float* w_low  = (const float*)d_in[2];
    const float* as_h   = (const float*)d_in[3];
    const float* as_l   = (const float*)d_in[4];
    float* out = (float*)d_out;

    cudaFuncSetAttribute(conv_hybrid_kernel,
                         cudaFuncAttributeMaxDynamicSharedMemorySize, CONV_SMEM);

    quant_weights_kernel<<<CC, 256>>>(w_high, as_h, 127.0f, 0);
    quant_weights_kernel<<<CC, 256>>>(w_low,  as_l,   7.0f, 1);
    mask_quant_kernel<<<dim3(WW / 8, HH / 8, BB), 256>>>(x, as_h, as_l);
    conv_hybrid_kernel<<<dim3(WW / 8, HH / 8, BB * 2), 256, CONV_SMEM>>>(out);
}